// round 5
// baseline (speedup 1.0000x reference)
#include <cuda_runtime.h>
#include <cuda_bf16.h>
#include <mma.h>
#include <cstdint>
#include <math.h>

using namespace nvcuda;

// Problem constants
#define BB 4
#define LL 512
#define DM 256
#define NL 6
#define DI 512
#define DS 16
#define DC 4
#define DTR 16
#define TT (BB * LL)        // 2048 tokens
#define XZW (2 * DI)        // 1024
#define RXW (DTR + 2 * DS)  // 48

// ---------------------------------------------------------------------------
// Scratch (device globals; no allocation allowed)
// ---------------------------------------------------------------------------
__device__ __align__(16) float g_scale[TT];
__device__ __align__(16) float g_xz[TT * XZW];
__device__ __align__(16) float g_u[TT * DI];
__device__ __align__(16) float g_xdbc[TT * RXW];
__device__ __align__(16) float g_delta[TT * DI];
__device__ __align__(16) float g_yg[TT * DI];

// ---------------------------------------------------------------------------
// RMSNorm scale: scale[t] = rsqrt(mean(x[t]^2)+eps). One warp per token.
// ---------------------------------------------------------------------------
__global__ void rms_scale_kernel(const float* __restrict__ x,
                                 float* __restrict__ scale) {
    int w = (blockIdx.x * blockDim.x + threadIdx.x) >> 5;
    int lane = threadIdx.x & 31;
    const float* xp = x + (size_t)w * DM + lane * 8;
    float4 a = *(const float4*)xp;
    float4 b = *(const float4*)(xp + 4);
    float sq = a.x*a.x + a.y*a.y + a.z*a.z + a.w*a.w
             + b.x*b.x + b.y*b.y + b.z*b.z + b.w*b.w;
#pragma unroll
    for (int o = 16; o > 0; o >>= 1) sq += __shfl_xor_sync(0xffffffffu, sq, o);
    if (lane == 0) scale[w] = rsqrtf(sq / (float)DM + 1e-5f);
}

// ---------------------------------------------------------------------------
// bf16-split TN GEMM via wmma (HMMA tensor cores):
// C[m,n] = sum_k (A[m,k]*arow[m]*acol[k]) * Bw[n,k]  (+bias[n]) (+addsrc[m,n])
// A: [M,K] fp32 row-major; Bw: [N,K] fp32 row-major. M%128==0, K%32==0.
// Block tile 128x64, BK=32, 256 threads = 8 warps (4 mrow x 2 ncol),
// warp tile 32x32 = 2x2 wmma m16n16k16 fragments.
// 2-term bf16 decomposition: Ah*Bh + Ah*Bl + Al*Bh (error ~2^-16).
// ---------------------------------------------------------------------------
#define ASTRIDE 40   // bf16 elements per A smem row (32 + 8 pad)
#define CSTRIDE 68   // f32 elements per C smem row (64 + 4 pad)

union SmemU {
    struct {
        __nv_bfloat16 ah[128][ASTRIDE];
        __nv_bfloat16 al[128][ASTRIDE];
        __nv_bfloat16 bh[64][ASTRIDE];
        __nv_bfloat16 bl[64][ASTRIDE];
    } t;
    float c[128][CSTRIDE];
};

__device__ __forceinline__ uint32_t pack_hi2(float x, float y) {
    __nv_bfloat162 h = __floats2bfloat162_rn(x, y);
    return *reinterpret_cast<uint32_t*>(&h);
}

__device__ __forceinline__ void hilo4(float4 v, uint2& hv, uint2& lv) {
    __nv_bfloat16 h0 = __float2bfloat16(v.x);
    __nv_bfloat16 h1 = __float2bfloat16(v.y);
    __nv_bfloat16 h2 = __float2bfloat16(v.z);
    __nv_bfloat16 h3 = __float2bfloat16(v.w);
    __nv_bfloat16 l0 = __float2bfloat16(v.x - __bfloat162float(h0));
    __nv_bfloat16 l1 = __float2bfloat16(v.y - __bfloat162float(h1));
    __nv_bfloat16 l2 = __float2bfloat16(v.z - __bfloat162float(h2));
    __nv_bfloat16 l3 = __float2bfloat16(v.w - __bfloat162float(h3));
    hv.x = (uint32_t)__bfloat16_as_ushort(h0) | ((uint32_t)__bfloat16_as_ushort(h1) << 16);
    hv.y = (uint32_t)__bfloat16_as_ushort(h2) | ((uint32_t)__bfloat16_as_ushort(h3) << 16);
    lv.x = (uint32_t)__bfloat16_as_ushort(l0) | ((uint32_t)__bfloat16_as_ushort(l1) << 16);
    lv.y = (uint32_t)__bfloat16_as_ushort(l2) | ((uint32_t)__bfloat16_as_ushort(l3) << 16);
}

__global__ void __launch_bounds__(256)
tc_gemm_kernel(const float* __restrict__ A, const float* __restrict__ Bw,
               const float* __restrict__ bias, const float* __restrict__ addsrc,
               const float* __restrict__ arow, const float* __restrict__ acol,
               float* __restrict__ C, int M, int N, int K) {
    __shared__ SmemU s;
    int tid = threadIdx.x;
    int wid = tid >> 5;
    int m0 = blockIdx.y * 128;
    int n0 = blockIdx.x * 64;
    int nt = N - n0; if (nt > 64) nt = 64;

    int wm = (wid & 3) * 32;   // warp m offset in tile
    int wn = (wid >> 2) * 32;  // warp n offset in tile

    wmma::fragment<wmma::accumulator, 16, 16, 16, float> acc[2][2];
#pragma unroll
    for (int i = 0; i < 2; i++)
#pragma unroll
        for (int j = 0; j < 2; j++) wmma::fill_fragment(acc[i][j], 0.f);

    // A loader: thread owns row tid>>1 (0..127), col half (tid&1)*16
    int a_row = tid >> 1;
    int a_cb = (tid & 1) * 16;
    float rs = arow ? arow[m0 + a_row] : 1.f;
    const float* arp = A + (size_t)(m0 + a_row) * K + a_cb;
    // B loader: thread owns row tid>>2 (0..63), col group (tid&3)*8
    int b_row = tid >> 2;
    int b_cb = (tid & 3) * 8;
    const float* brp = Bw + (size_t)(n0 + b_row) * K + b_cb;
    bool b_valid = b_row < nt;

    for (int k0 = 0; k0 < K; k0 += 32) {
        // ---- stage A tile (128x32) as hi/lo bf16 ----
#pragma unroll
        for (int c = 0; c < 16; c += 4) {
            float4 v = *(const float4*)(arp + k0 + c);
            if (acol) {
                float4 wv = *(const float4*)(acol + k0 + a_cb + c);
                v.x *= wv.x; v.y *= wv.y; v.z *= wv.z; v.w *= wv.w;
            }
            v.x *= rs; v.y *= rs; v.z *= rs; v.w *= rs;
            uint2 hv, lv;
            hilo4(v, hv, lv);
            *(uint2*)&s.t.ah[a_row][a_cb + c] = hv;
            *(uint2*)&s.t.al[a_row][a_cb + c] = lv;
        }
        // ---- stage B tile (64x32) as hi/lo bf16 ----
        if (b_valid) {
#pragma unroll
            for (int c = 0; c < 8; c += 4) {
                float4 v = *(const float4*)(brp + k0 + c);
                uint2 hv, lv;
                hilo4(v, hv, lv);
                *(uint2*)&s.t.bh[b_row][b_cb + c] = hv;
                *(uint2*)&s.t.bl[b_row][b_cb + c] = lv;
            }
        } else {
            uint2 z = make_uint2(0u, 0u);
#pragma unroll
            for (int c = 0; c < 8; c += 4) {
                *(uint2*)&s.t.bh[b_row][b_cb + c] = z;
                *(uint2*)&s.t.bl[b_row][b_cb + c] = z;
            }
        }
        __syncthreads();

        // ---- MMA: 2 k-steps x (2x2 tiles) x 3 split terms ----
#pragma unroll
        for (int ks = 0; ks < 32; ks += 16) {
            wmma::fragment<wmma::matrix_a, 16, 16, 16, __nv_bfloat16, wmma::row_major> fah[2], fal[2];
            wmma::fragment<wmma::matrix_b, 16, 16, 16, __nv_bfloat16, wmma::col_major> fbh[2], fbl[2];
#pragma unroll
            for (int i = 0; i < 2; i++) {
                wmma::load_matrix_sync(fah[i], &s.t.ah[wm + i * 16][ks], ASTRIDE);
                wmma::load_matrix_sync(fal[i], &s.t.al[wm + i * 16][ks], ASTRIDE);
            }
#pragma unroll
            for (int j = 0; j < 2; j++) {
                wmma::load_matrix_sync(fbh[j], &s.t.bh[wn + j * 16][ks], ASTRIDE);
                wmma::load_matrix_sync(fbl[j], &s.t.bl[wn + j * 16][ks], ASTRIDE);
            }
#pragma unroll
            for (int i = 0; i < 2; i++)
#pragma unroll
                for (int j = 0; j < 2; j++) {
                    wmma::mma_sync(acc[i][j], fah[i], fbh[j], acc[i][j]);
                    wmma::mma_sync(acc[i][j], fah[i], fbl[j], acc[i][j]);
                    wmma::mma_sync(acc[i][j], fal[i], fbh[j], acc[i][j]);
                }
        }
        __syncthreads();
    }

    // ---- epilogue: accum -> smem -> (bias, residual) -> global ----
#pragma unroll
    for (int i = 0; i < 2; i++)
#pragma unroll
        for (int j = 0; j < 2; j++)
            wmma::store_matrix_sync(&s.c[wm + i * 16][wn + j * 16], acc[i][j],
                                    CSTRIDE, wmma::mem_row_major);
    __syncthreads();

    int e_row = tid >> 1;            // 0..127
    int e_cb = (tid & 1) * 32;       // 0 or 32
    int gm = m0 + e_row;
    float* cp = C + (size_t)gm * N + n0;
    const float* ap2 = addsrc ? addsrc + (size_t)gm * N + n0 : nullptr;
#pragma unroll
    for (int c = 0; c < 32; c += 4) {
        int col = e_cb + c;
        if (col >= nt) break;
        float4 v = *(float4*)&s.c[e_row][col];
        if (bias) {
            float4 b = *(const float4*)(bias + n0 + col);
            v.x += b.x; v.y += b.y; v.z += b.z; v.w += b.w;
        }
        if (ap2) {
            float4 a = *(const float4*)(ap2 + col);
            v.x += a.x; v.y += a.y; v.z += a.z; v.w += a.w;
        }
        *(float4*)(cp + col) = v;
    }
}

// ---------------------------------------------------------------------------
// Causal depthwise conv (width 4) + SiLU. xz layout [t, 1024]; xin = first 512.
// ---------------------------------------------------------------------------
__global__ void conv_silu_kernel(const float* __restrict__ xz,
                                 const float* __restrict__ cw,
                                 float* __restrict__ u) {
    int idx = blockIdx.x * blockDim.x + threadIdx.x;
    int t = idx >> 9;
    int d = idx & 511;
    int l = t & 511;
    float acc = 0.f;
#pragma unroll
    for (int j = 0; j < 4; j++) {
        int ll = l - 3 + j;
        if (ll >= 0) acc = fmaf(cw[d * 4 + j], xz[(size_t)(t - 3 + j) * XZW + d], acc);
    }
    float s = 1.f / (1.f + __expf(-acc));
    u[idx] = acc * s;
}

// ---------------------------------------------------------------------------
// delta = softplus(dt @ dt_w^T + dt_b), dt = xdbc[:, :16]
// ---------------------------------------------------------------------------
__global__ void delta_kernel(const float* __restrict__ xdbc,
                             const float* __restrict__ dtw,
                             const float* __restrict__ dtb,
                             float* __restrict__ delta) {
    int idx = blockIdx.x * blockDim.x + threadIdx.x;
    int t = idx >> 9;
    int d = idx & 511;
    float s = dtb[d];
#pragma unroll
    for (int r = 0; r < DTR; r++) s = fmaf(xdbc[t * RXW + r], dtw[d * DTR + r], s);
    delta[idx] = (s > 20.f) ? s : log1pf(__expf(s));
}

// ---------------------------------------------------------------------------
// Selective scan + fused gate. Thread = (b, d, n). 16-lane groups share d.
// yg = (y + u*D) * silu(z) written at n==0.
// ---------------------------------------------------------------------------
__global__ void scan_gate_kernel(const float* __restrict__ delta,
                                 const float* __restrict__ u,
                                 const float* __restrict__ xdbc,
                                 const float* __restrict__ A_log,
                                 const float* __restrict__ xz,
                                 const float* __restrict__ Dp,
                                 float* __restrict__ yg) {
    int b = blockIdx.x >> 5;
    int dbase = (blockIdx.x & 31) << 4;
    int n = threadIdx.x & 15;
    int dg = threadIdx.x >> 4;
    int d = dbase + dg;
    float Ac = -__expf(A_log[d * DS + n]);
    float Dv = Dp[d];
    float h = 0.f;
    int tbase = b << 9;
    for (int l = 0; l < LL; l++) {
        int t = tbase + l;
        float del = delta[(size_t)t * DI + d];
        float uu = u[(size_t)t * DI + d];
        float Bn = xdbc[t * RXW + DTR + n];
        float Cn = xdbc[t * RXW + DTR + DS + n];
        h = fmaf(__expf(del * Ac), h, del * uu * Bn);
        float yp = h * Cn;
#pragma unroll
        for (int o = 8; o > 0; o >>= 1) yp += __shfl_xor_sync(0xffffffffu, yp, o, 16);
        if (n == 0) {
            float z = xz[(size_t)t * XZW + DI + d];
            float sz = z / (1.f + __expf(-z));
            yg[(size_t)t * DI + d] = (yp + uu * Dv) * sz;
        }
    }
}

// ---------------------------------------------------------------------------
// Host launcher
// ---------------------------------------------------------------------------
extern "C" void kernel_launch(void* const* d_in, const int* in_sizes, int n_in,
                              void* d_out, int out_size) {
    const float* x      = (const float*)d_in[0];
    const float* norm_w = (const float*)d_in[1];
    const float* W_in   = (const float*)d_in[2];
    const float* b_in   = (const float*)d_in[3];
    const float* conv_w = (const float*)d_in[4];
    const float* W_x    = (const float*)d_in[5];
    const float* dt_w   = (const float*)d_in[6];
    const float* dt_b   = (const float*)d_in[7];
    const float* A_log  = (const float*)d_in[8];
    const float* Dp     = (const float*)d_in[9];
    const float* W_out  = (const float*)d_in[10];
    const float* b_out  = (const float*)d_in[11];
    float* xcur = (float*)d_out;

    float *scale, *xz, *u, *xdbc, *delta, *yg;
    cudaGetSymbolAddress((void**)&scale, g_scale);
    cudaGetSymbolAddress((void**)&xz, g_xz);
    cudaGetSymbolAddress((void**)&u, g_u);
    cudaGetSymbolAddress((void**)&xdbc, g_xdbc);
    cudaGetSymbolAddress((void**)&delta, g_delta);
    cudaGetSymbolAddress((void**)&yg, g_yg);

    cudaMemcpyAsync(xcur, x, (size_t)TT * DM * sizeof(float),
                    cudaMemcpyDeviceToDevice);

    const int ew_blocks = (TT * DI) / 256;  // 4096

    for (int i = 0; i < NL; i++) {
        // rmsnorm scale per token (fused into in-proj loader)
        rms_scale_kernel<<<TT / 8, 256>>>(xcur, scale);

        // in-proj: [2048,1024] = rmsnorm(x) @ W_in^T + b_in
        tc_gemm_kernel<<<dim3(XZW / 64, TT / 128), 256>>>(
            xcur, W_in + (size_t)i * XZW * DM, b_in + (size_t)i * XZW, nullptr,
            scale, norm_w + (size_t)i * DM,
            xz, TT, XZW, DM);

        conv_silu_kernel<<<ew_blocks, 256>>>(xz, conv_w + (size_t)i * DI * DC, u);

        // x-proj: [2048,48] = u @ W_x^T
        tc_gemm_kernel<<<dim3(1, TT / 128), 256>>>(
            u, W_x + (size_t)i * RXW * DI, nullptr, nullptr, nullptr, nullptr,
            xdbc, TT, RXW, DI);

        delta_kernel<<<ew_blocks, 256>>>(xdbc, dt_w + (size_t)i * DI * DTR,
                                         dt_b + (size_t)i * DI, delta);

        scan_gate_kernel<<<BB * (DI / 16), 256>>>(
            delta, u, xdbc, A_log + (size_t)i * DI * DS, xz,
            Dp + (size_t)i * DI, yg);

        // out-proj + residual: xcur = yg @ W_out^T + b_out + xcur
        tc_gemm_kernel<<<dim3(DM / 64, TT / 128), 256>>>(
            yg, W_out + (size_t)i * DM * DI, b_out + (size_t)i * DM, xcur,
            nullptr, nullptr,
            xcur, TT, DM, DI);
    }
}